// round 1
// baseline (speedup 1.0000x reference)
#include <cuda_runtime.h>

#define D       128
#define NCOLS   384
#define NMAX    50000

#define BM 128
#define BN 128
#define BK 16
#define PAD 4

// Scratch (no allocations allowed): pre-transformed, pre-scaled per-relation
// node features [2][N][128] and the concatenated scaled weight [128][384].
__device__ float g_hrel[2ull * NMAX * D];
__device__ float g_wcat[D * NCOLS];

static __device__ __forceinline__ float2 unpack2(unsigned long long u) {
    float2 r;
    asm("mov.b64 {%0, %1}, %2;" : "=f"(r.x), "=f"(r.y) : "l"(u));
    return r;
}

// Build Wcat = [sqrt(a)*W0 | sqrt(a)*W1 | sqrt(1-a)*loopW], all scales = 0.70710678
__global__ void prep_wcat(const float* __restrict__ weight,
                          const float* __restrict__ loopw) {
    int idx = blockIdx.x * blockDim.x + threadIdx.x;
    if (idx >= D * NCOLS) return;
    int d = idx / NCOLS;
    int j = idx % NCOLS;
    const float s = 0.70710678118654752440f;
    float v;
    if (j < 2 * D) {
        int r = (j >= D);
        v = weight[(size_t)r * D * D + (size_t)d * D + (j & (D - 1))];
    } else {
        v = loopw[(size_t)d * D + (j - 2 * D)];
    }
    g_wcat[idx] = s * v;
}

// Fused GEMM: Y[N, 384] = feat[N,128] @ Wcat[128,384]
//   col-block 0 -> g_hrel[0], col-block 1 -> g_hrel[1],
//   col-block 2 -> out = bias + Y  (loop message init)
// fp32 math via packed fma.rn.f32x2 (FFMA2): exact fp32, 2x FFMA rate.
__global__ __launch_bounds__(256, 2) void gemm_kernel(
    const float* __restrict__ feat,
    const float* __restrict__ bias,
    float* __restrict__ out,
    int N)
{
    __shared__ float As[BK][BM + PAD];   // transposed: As[k][m]
    __shared__ float Bs[BK][BN];         // Bs[k][n]

    const int tid = threadIdx.x;
    const int tx  = tid & 15;            // 16 col-groups of 8
    const int ty  = tid >> 4;            // 16 row-groups of 8
    const int m0  = blockIdx.x * BM;
    const int cb  = blockIdx.y;          // 0,1: h_rel ; 2: out/loop

    unsigned long long acc[8][4];        // 8 rows x 4 f32x2 col-pairs
#pragma unroll
    for (int i = 0; i < 8; i++)
#pragma unroll
        for (int j = 0; j < 4; j++) acc[i][j] = 0ull;

    for (int k0 = 0; k0 < D; k0 += BK) {
        // A tile: 128 rows x 16 k, transposed into smem
#pragma unroll
        for (int t = 0; t < 2; t++) {
            int linear = tid + t * 256;       // 0..511
            int row = linear >> 2;            // 0..127
            int c   = linear & 3;             // float4 index along k
            int gm  = m0 + row;
            float4 v = make_float4(0.f, 0.f, 0.f, 0.f);
            if (gm < N) v = *(const float4*)&feat[(size_t)gm * D + k0 + c * 4];
            As[c * 4 + 0][row] = v.x;
            As[c * 4 + 1][row] = v.y;
            As[c * 4 + 2][row] = v.z;
            As[c * 4 + 3][row] = v.w;
        }
        // B tile: 16 k x 128 n
#pragma unroll
        for (int t = 0; t < 2; t++) {
            int linear = tid + t * 256;
            int row = linear >> 5;            // 0..15
            int c   = linear & 31;            // float4 index along n
            float4 v = *(const float4*)&g_wcat[(size_t)(k0 + row) * NCOLS + cb * BN + c * 4];
            *(float4*)&Bs[row][c * 4] = v;
        }
        __syncthreads();

#pragma unroll
        for (int kk = 0; kk < BK; kk++) {
            float4 alo = *(const float4*)&As[kk][ty * 8];
            float4 ahi = *(const float4*)&As[kk][ty * 8 + 4];
            ulonglong2 bA = *(const ulonglong2*)&Bs[kk][tx * 8];
            ulonglong2 bB = *(const ulonglong2*)&Bs[kk][tx * 8 + 4];
            unsigned long long b2[4] = { bA.x, bA.y, bB.x, bB.y };
            float a[8] = { alo.x, alo.y, alo.z, alo.w, ahi.x, ahi.y, ahi.z, ahi.w };
#pragma unroll
            for (int i = 0; i < 8; i++) {
                unsigned long long a2;
                asm("mov.b64 %0, {%1, %1};" : "=l"(a2) : "f"(a[i]));
#pragma unroll
                for (int j = 0; j < 4; j++) {
                    asm("fma.rn.f32x2 %0, %1, %2, %0;"
                        : "+l"(acc[i][j]) : "l"(a2), "l"(b2[j]));
                }
            }
        }
        __syncthreads();
    }

    // Epilogue
    if (cb < 2) {
        float* dstbase = &g_hrel[(size_t)cb * N * D];
#pragma unroll
        for (int i = 0; i < 8; i++) {
            int gm = m0 + ty * 8 + i;
            if (gm >= N) continue;
            float2 v0 = unpack2(acc[i][0]);
            float2 v1 = unpack2(acc[i][1]);
            float2 v2 = unpack2(acc[i][2]);
            float2 v3 = unpack2(acc[i][3]);
            *(float4*)&dstbase[(size_t)gm * D + tx * 8]     = make_float4(v0.x, v0.y, v1.x, v1.y);
            *(float4*)&dstbase[(size_t)gm * D + tx * 8 + 4] = make_float4(v2.x, v2.y, v3.x, v3.y);
        }
    } else {
        float4 bl = *(const float4*)&bias[tx * 8];
        float4 bh = *(const float4*)&bias[tx * 8 + 4];
#pragma unroll
        for (int i = 0; i < 8; i++) {
            int gm = m0 + ty * 8 + i;
            if (gm >= N) continue;
            float2 v0 = unpack2(acc[i][0]);
            float2 v1 = unpack2(acc[i][1]);
            float2 v2 = unpack2(acc[i][2]);
            float2 v3 = unpack2(acc[i][3]);
            *(float4*)&out[(size_t)gm * D + tx * 8] =
                make_float4(v0.x + bl.x, v0.y + bl.y, v1.x + bl.z, v1.y + bl.w);
            *(float4*)&out[(size_t)gm * D + tx * 8 + 4] =
                make_float4(v2.x + bh.x, v2.y + bh.y, v3.x + bh.z, v3.y + bh.w);
        }
    }
}

// One warp per edge: gather the (pre-scaled) transformed src row from the
// right relation plane and vector-atomicAdd it into the dst row.
__global__ __launch_bounds__(256) void edge_scatter(
    const int* __restrict__ src,
    const int* __restrict__ dst,
    const int* __restrict__ et,
    float* __restrict__ out,
    int E, int N)
{
    int gw = (blockIdx.x * 256 + threadIdx.x) >> 5;
    if (gw >= E) return;
    int lane = threadIdx.x & 31;
    int s = __ldg(&src[gw]);
    int d = __ldg(&dst[gw]);
    int r = __ldg(&et[gw]);
    float4 v = *(const float4*)&g_hrel[((size_t)r * N + (size_t)s) * D + lane * 4];
    atomicAdd((float4*)&out[(size_t)d * D + lane * 4], v);
}

extern "C" void kernel_launch(void* const* d_in, const int* in_sizes, int n_in,
                              void* d_out, int out_size) {
    const float* feat   = (const float*)d_in[0];
    const int*   src    = (const int*)d_in[1];
    const int*   dst    = (const int*)d_in[2];
    const int*   etypes = (const int*)d_in[3];
    const float* weight = (const float*)d_in[4];
    const float* loopw  = (const float*)d_in[5];
    const float* bias   = (const float*)d_in[6];
    float* out = (float*)d_out;

    int N = in_sizes[0] / D;
    int E = in_sizes[1];

    prep_wcat<<<(D * NCOLS + 255) / 256, 256>>>(weight, loopw);

    dim3 grid((N + BM - 1) / BM, 3);
    gemm_kernel<<<grid, 256>>>(feat, bias, out, N);

    int nwarp_blocks = (E * 32 + 255) / 256;
    edge_scatter<<<nwarp_blocks, 256>>>(src, dst, etypes, out, E, N);
}

// round 2
// speedup vs baseline: 1.5811x; 1.5811x over previous
#include <cuda_runtime.h>

#define D       128
#define NCOLS   384
#define NMAX    50000

#define BM 128
#define BK 32
#define SST 136   // smem row stride (floats): 136 mod 32 = 8 -> 8t+g conflict-free frags

// Scratch: pre-transformed, pre-scaled per-relation node features [2][N][128]
// and the concatenated scaled weight [128][384].
__device__ float g_hrel[2ull * NMAX * D];
__device__ float g_wcat[D * NCOLS];

// Build Wcat = [sqrt(a)*W0 | sqrt(a)*W1 | sqrt(1-a)*loopW], all scales = 0.70710678
__global__ void prep_wcat(const float* __restrict__ weight,
                          const float* __restrict__ loopw) {
    int idx = blockIdx.x * blockDim.x + threadIdx.x;
    if (idx >= D * NCOLS) return;
    int d = idx / NCOLS;
    int j = idx % NCOLS;
    const float s = 0.70710678118654752440f;
    float v;
    if (j < 2 * D) {
        int r = (j >= D);
        v = weight[(size_t)r * D * D + (size_t)d * D + (j & (D - 1))];
    } else {
        v = loopw[(size_t)d * D + (j - 2 * D)];
    }
    g_wcat[idx] = s * v;
}

static __device__ __forceinline__ unsigned f2tf(float x) {
    unsigned r;
    asm("cvt.rna.tf32.f32 %0, %1;" : "=r"(r) : "f"(x));
    return r;
}

static __device__ __forceinline__ void mma_tf32(
    float c[4], unsigned a0, unsigned a1, unsigned a2, unsigned a3,
    unsigned b0, unsigned b1)
{
    asm volatile(
        "mma.sync.aligned.m16n8k8.row.col.f32.tf32.tf32.f32 "
        "{%0,%1,%2,%3}, {%4,%5,%6,%7}, {%8,%9}, {%0,%1,%2,%3};"
        : "+f"(c[0]), "+f"(c[1]), "+f"(c[2]), "+f"(c[3])
        : "r"(a0), "r"(a1), "r"(a2), "r"(a3), "r"(b0), "r"(b1));
}

// Tensor-core GEMM: Y[N, 384] = feat[N,128] @ Wcat[128,384] via tf32 mma.sync.
//   col-block 0 -> g_hrel[0], col-block 1 -> g_hrel[1],
//   col-block 2 -> out = bias + Y (loop message init)
__global__ __launch_bounds__(256, 2) void gemm_tc(
    const float* __restrict__ feat,
    const float* __restrict__ bias,
    float* __restrict__ out,
    int N)
{
    __shared__ float As[BK][SST];  // [k][m], tf32-rounded bits
    __shared__ float Bs[BK][SST];  // [k][n], tf32-rounded bits

    const int tid  = threadIdx.x;
    const int lane = tid & 31;
    const int wid  = tid >> 5;
    const int g    = lane >> 2;      // 0..7
    const int t    = lane & 3;       // 0..3
    const int wm   = (wid & 3) * 32; // warp m-offset in block tile
    const int wn   = (wid >> 2) * 64;// warp n-offset in block tile
    const int m0   = blockIdx.x * BM;
    const int cb   = blockIdx.y;     // 0,1: h_rel ; 2: out/loop

    float acc[2][8][4];              // [m16 tile][n8 tile][frag]
#pragma unroll
    for (int i = 0; i < 2; i++)
#pragma unroll
        for (int j = 0; j < 8; j++)
#pragma unroll
            for (int q = 0; q < 4; q++) acc[i][j][q] = 0.f;

    for (int k0 = 0; k0 < D; k0 += BK) {
        // ---- A tile: feat[m0..m0+128)[k0..k0+32) transposed into As[k][m]
        {
            int row = tid >> 1;                 // 0..127
            int gm  = m0 + row;
#pragma unroll
            for (int i = 0; i < 4; i++) {
                int c = (tid & 1) * 4 + i;      // float4 index along k (0..7)
                float4 v = make_float4(0.f, 0.f, 0.f, 0.f);
                if (gm < N) v = *(const float4*)&feat[(size_t)gm * D + k0 + c * 4];
                As[c * 4 + 0][row] = __uint_as_float(f2tf(v.x));
                As[c * 4 + 1][row] = __uint_as_float(f2tf(v.y));
                As[c * 4 + 2][row] = __uint_as_float(f2tf(v.z));
                As[c * 4 + 3][row] = __uint_as_float(f2tf(v.w));
            }
        }
        // ---- B tile: wcat[k0..k0+32)[cb*128..+128) row-major into Bs[k][n]
#pragma unroll
        for (int tt = 0; tt < 4; tt++) {
            int linear = tid + tt * 256;        // 0..1023
            int row = linear >> 5;              // 0..31
            int c   = linear & 31;              // float4 index along n
            float4 v = *(const float4*)&g_wcat[(size_t)(k0 + row) * NCOLS + cb * D + c * 4];
            float4 w;
            w.x = __uint_as_float(f2tf(v.x));
            w.y = __uint_as_float(f2tf(v.y));
            w.z = __uint_as_float(f2tf(v.z));
            w.w = __uint_as_float(f2tf(v.w));
            *(float4*)&Bs[row][c * 4] = w;
        }
        __syncthreads();

#pragma unroll
        for (int kk = 0; kk < BK; kk += 8) {
            unsigned a[2][4];
#pragma unroll
            for (int mt = 0; mt < 2; mt++) {
                int mb = wm + mt * 16;
                a[mt][0] = __float_as_uint(As[kk + t]    [mb + g]);
                a[mt][1] = __float_as_uint(As[kk + t]    [mb + g + 8]);
                a[mt][2] = __float_as_uint(As[kk + t + 4][mb + g]);
                a[mt][3] = __float_as_uint(As[kk + t + 4][mb + g + 8]);
            }
#pragma unroll
            for (int nt = 0; nt < 8; nt++) {
                int nb = wn + nt * 8;
                unsigned b0 = __float_as_uint(Bs[kk + t]    [nb + g]);
                unsigned b1 = __float_as_uint(Bs[kk + t + 4][nb + g]);
                mma_tf32(acc[0][nt], a[0][0], a[0][1], a[0][2], a[0][3], b0, b1);
                mma_tf32(acc[1][nt], a[1][0], a[1][1], a[1][2], a[1][3], b0, b1);
            }
        }
        __syncthreads();
    }

    // ---- Epilogue: c0,c1 at (g, 2t), c2,c3 at (g+8, 2t) per n8 tile
#pragma unroll
    for (int mt = 0; mt < 2; mt++) {
        int gm_lo = m0 + wm + mt * 16 + g;
        int gm_hi = gm_lo + 8;
#pragma unroll
        for (int nt = 0; nt < 8; nt++) {
            int col = wn + nt * 8 + 2 * t;       // 0..127 within col-block
            if (cb < 2) {
                float* dstb = &g_hrel[(size_t)cb * N * D];
                if (gm_lo < N)
                    *(float2*)&dstb[(size_t)gm_lo * D + col] =
                        make_float2(acc[mt][nt][0], acc[mt][nt][1]);
                if (gm_hi < N)
                    *(float2*)&dstb[(size_t)gm_hi * D + col] =
                        make_float2(acc[mt][nt][2], acc[mt][nt][3]);
            } else {
                float2 bv = *(const float2*)&bias[col];
                if (gm_lo < N)
                    *(float2*)&out[(size_t)gm_lo * D + col] =
                        make_float2(acc[mt][nt][0] + bv.x, acc[mt][nt][1] + bv.y);
                if (gm_hi < N)
                    *(float2*)&out[(size_t)gm_hi * D + col] =
                        make_float2(acc[mt][nt][2] + bv.x, acc[mt][nt][3] + bv.y);
            }
        }
    }
}

// One warp per edge: gather the (pre-scaled) transformed src row from the
// right relation plane and vector-atomicAdd it into the dst row.
__global__ __launch_bounds__(256) void edge_scatter(
    const int* __restrict__ src,
    const int* __restrict__ dst,
    const int* __restrict__ et,
    float* __restrict__ out,
    int E, int N)
{
    int gw = (blockIdx.x * 256 + threadIdx.x) >> 5;
    if (gw >= E) return;
    int lane = threadIdx.x & 31;
    int s = __ldg(&src[gw]);
    int d = __ldg(&dst[gw]);
    int r = __ldg(&et[gw]);
    float4 v = *(const float4*)&g_hrel[((size_t)r * N + (size_t)s) * D + lane * 4];
    atomicAdd((float4*)&out[(size_t)d * D + lane * 4], v);
}

extern "C" void kernel_launch(void* const* d_in, const int* in_sizes, int n_in,
                              void* d_out, int out_size) {
    const float* feat   = (const float*)d_in[0];
    const int*   src    = (const int*)d_in[1];
    const int*   dst    = (const int*)d_in[2];
    const int*   etypes = (const int*)d_in[3];
    const float* weight = (const float*)d_in[4];
    const float* loopw  = (const float*)d_in[5];
    const float* bias   = (const float*)d_in[6];
    float* out = (float*)d_out;

    int N = in_sizes[0] / D;
    int E = in_sizes[1];

    prep_wcat<<<(D * NCOLS + 255) / 256, 256>>>(weight, loopw);

    dim3 grid((N + BM - 1) / BM, 3);
    gemm_tc<<<grid, 256>>>(feat, bias, out, N);

    int nwarp_blocks = (E * 32 + 255) / 256;
    edge_scatter<<<nwarp_blocks, 256>>>(src, dst, etypes, out, E, N);
}